// round 4
// baseline (speedup 1.0000x reference)
#include <cuda_runtime.h>
#include <cstdint>

#define BS   128
#define T    512
#define E    512
#define NGRP 8          // batch groups
#define RPG  16         // batch rows per group
#define CPG  16         // CTAs per group (column split)
#define NC   32         // output cols per CTA
#define RPAD 516        // padded row stride (floats) for state tiles in smem
#define NTHR 512

// output layout offsets (float elements)
#define ACT_OFF  0
#define EC3HIS   131072
#define EC5HIS   33685504
#define CA1HIS   67239936
#define EC3F     100794368
#define EC5F     100859904
#define CA1F     100925440

// device scratch (allocation-free rule: static __device__ arrays)
__device__ float    g_drive[T * E];      // ca3drive[t][j]
__device__ float    g_ex_ca1[BS * E];    // per-step ca1 exchange
__device__ float    g_ex_ec3[BS * E];    // per-step ec3 exchange
__device__ unsigned g_bar_cnt[16];
__device__ unsigned g_bar_gen[16];
__device__ int      g_flag_other;        // mask-word outside {0,1,1.0f}
__device__ int      g_flag_float;        // mask-word == 0x3F800000
__device__ int      g_flag_one;          // mask-word == 1

// smem layout (floats)
#define SM_W1    0
#define SM_W2    (512 * NC)                  // 16384
#define SM_X     (2 * 512 * NC)              // 32768
#define SM_C     (SM_X + RPG * RPAD)         // 41024
#define SM_RED   (SM_C + RPG * RPAD)         // 49280
#define SM_EC5   (SM_RED + 2048)             // 51328
#define SM_WACT  (SM_EC5 + 512)              // 51840
#define SM_BIAS  (SM_WACT + 1024)            // 52864
#define SM_ACTB  (SM_BIAS + 32)              // 52896
#define SM_FLOATS (SM_ACTB + 4)              // 52900
#define SMEM_BYTES (SM_FLOATS * 4)           // 211600 B

// ---------------- mask-dtype detection ----------------
__global__ void init_flags_kernel() {
    g_flag_other = 0; g_flag_float = 0; g_flag_one = 0;
}

// Scan first nwords 32-bit words of the mask buffer and classify encoding.
__global__ void detect_mask_kernel(const unsigned* __restrict__ m, int nwords) {
    int i = blockIdx.x * blockDim.x + threadIdx.x;
    int stride = gridDim.x * blockDim.x;
    int other = 0, fl = 0, one = 0;
    for (; i < nwords; i += stride) {
        unsigned w = m[i];
        if (w == 0u) continue;
        if (w == 0x3F800000u)      fl = 1;
        else if (w == 1u)          one = 1;
        else                       other = 1;
    }
    if (other) g_flag_other = 1;
    if (fl)    g_flag_float = 1;
    if (one)   g_flag_one   = 1;
}

// sense-reversal barrier over n CTAs sharing counter idx
__device__ __forceinline__ void group_barrier(int idx, unsigned n) {
    __syncthreads();
    if (threadIdx.x == 0) {
        __threadfence();
        volatile unsigned* vcnt = g_bar_cnt;
        volatile unsigned* vgen = g_bar_gen;
        unsigned gen0 = vgen[idx];
        unsigned a = atomicAdd(&g_bar_cnt[idx], 1u);
        if (a == n - 1u) {
            vcnt[idx] = 0u;
            __threadfence();
            vgen[idx] = gen0 + 1u;
        } else {
            while (vgen[idx] == gen0) { }
        }
        __threadfence();
    }
    __syncthreads();
}

// z[16][32] = xs(16 x 512, RPAD stride) @ Ws(512 x 32)
// 16 warps: warp = q + 4*p, q = row-quad, p = k-partition (128 k each).
// lane: rq = lane>>3 (row in quad), cg = lane&7 (4-col group).
// Returns z for output element (r = tid>>5, j = tid&31).
__device__ __forceinline__ float gemm_zval(const float* __restrict__ Ws,
                                           const float* __restrict__ xs,
                                           float* __restrict__ red) {
    const int tid  = threadIdx.x;
    const int warp = tid >> 5, lane = tid & 31;
    const int q  = warp & 3,  p  = warp >> 2;
    const int rq = lane >> 3, cg = lane & 7;
    const int r  = (q << 2) + rq;

    const float* xrow = xs + r * RPAD + (p << 7);
    const float* wb   = Ws + (p << 7) * NC + (cg << 2);

    float4 acc = make_float4(0.f, 0.f, 0.f, 0.f);
#pragma unroll 8
    for (int k = 0; k < 128; k += 4) {
        float4 xv = *(const float4*)(xrow + k);
        float4 w0 = *(const float4*)(wb + (k + 0) * NC);
        float4 w1 = *(const float4*)(wb + (k + 1) * NC);
        float4 w2 = *(const float4*)(wb + (k + 2) * NC);
        float4 w3 = *(const float4*)(wb + (k + 3) * NC);
        acc.x = fmaf(xv.x, w0.x, acc.x); acc.y = fmaf(xv.x, w0.y, acc.y);
        acc.z = fmaf(xv.x, w0.z, acc.z); acc.w = fmaf(xv.x, w0.w, acc.w);
        acc.x = fmaf(xv.y, w1.x, acc.x); acc.y = fmaf(xv.y, w1.y, acc.y);
        acc.z = fmaf(xv.y, w1.z, acc.z); acc.w = fmaf(xv.y, w1.w, acc.w);
        acc.x = fmaf(xv.z, w2.x, acc.x); acc.y = fmaf(xv.z, w2.y, acc.y);
        acc.z = fmaf(xv.z, w2.z, acc.z); acc.w = fmaf(xv.z, w2.w, acc.w);
        acc.x = fmaf(xv.w, w3.x, acc.x); acc.y = fmaf(xv.w, w3.y, acc.y);
        acc.z = fmaf(xv.w, w3.z, acc.z); acc.w = fmaf(xv.w, w3.w, acc.w);
    }
    *(float4*)(red + (p * 16 + r) * NC + (cg << 2)) = acc;
    __syncthreads();
    const int rr = tid >> 5, jj = tid & 31;
    return red[rr * NC + jj] + red[512 + rr * NC + jj] +
           red[1024 + rr * NC + jj] + red[1536 + rr * NC + jj];
}

__global__ void __launch_bounds__(NTHR, 1)
rnn_kernel(const float* __restrict__ ec3input,
           const float* __restrict__ ec3_last,
           const float* __restrict__ ec5_last,
           const float* __restrict__ ca1_last,   // unused by reference
           const float* __restrict__ ca1bias,
           const float* __restrict__ wca3ca1,
           const float* __restrict__ wec3ca1,
           const float* __restrict__ wca1ec5,
           const float* __restrict__ wca1act,
           const float* __restrict__ actbias,
           const void* __restrict__ noise_mask,
           const int* __restrict__ ca3order,
           float* __restrict__ out) {
    extern __shared__ float smem[];
    float* W1s    = smem + SM_W1;
    float* W2s    = smem + SM_W2;
    float* x_s    = smem + SM_X;
    float* c_s    = smem + SM_C;
    float* red    = smem + SM_RED;
    float* ec5s   = smem + SM_EC5;
    float* wact_s = smem + SM_WACT;
    float* bias_s = smem + SM_BIAS;
    float* actb_s = smem + SM_ACTB;

    const int tid = threadIdx.x;
    const int bx  = blockIdx.x;
    const int g   = bx >> 4;     // batch group
    const int ci  = bx & 15;     // column CTA within group
    const int j0  = ci * NC;
    const int r   = tid >> 5;    // local row 0..15
    const int j   = tid & 31;    // local col 0..31
    const int b   = g * RPG + r; // global batch row
    const int col = j0 + j;      // global hidden col

    // mask encoding: 0 = uint8/bool, 1 = int32, 2 = float32
    const int mmode = g_flag_other ? 0 : (g_flag_float ? 2 : (g_flag_one ? 1 : 0));
    const uint8_t* nm_u8  = (const uint8_t*)noise_mask;
    const int*     nm_i32 = (const int*)noise_mask;
    const float*   nm_f32 = (const float*)noise_mask;

    // ---------------- Phase 0: ca3drive precompute ----------------
    // CTA bx computes drive rows t = 4*bx .. 4*bx+3 (all 512 cols).
    {
        float* ca3v = x_s;  // reuse 4*512 floats of x_s region
        const float stepv = 614.4f / 511.0f;
        const int   ordc  = ca3order[tid];
        const float cen   = -51.2f + stepv * (float)ordc;
#pragma unroll
        for (int i = 0; i < 4; i++) {
            float d = cen - (float)(4 * bx + i);
            ca3v[i * 512 + tid] = expf(-d * d * 0.02f);
        }
        __syncthreads();
        float a0 = 0.f, a1 = 0.f, a2 = 0.f, a3 = 0.f;
#pragma unroll 4
        for (int c = 0; c < 512; c++) {
            float wv = wca3ca1[c * 512 + tid];
            a0 = fmaf(ca3v[c],        wv, a0);
            a1 = fmaf(ca3v[512 + c],  wv, a1);
            a2 = fmaf(ca3v[1024 + c], wv, a2);
            a3 = fmaf(ca3v[1536 + c], wv, a3);
        }
        g_drive[(4 * bx + 0) * 512 + tid] = a0;
        g_drive[(4 * bx + 1) * 512 + tid] = a1;
        g_drive[(4 * bx + 2) * 512 + tid] = a2;
        g_drive[(4 * bx + 3) * 512 + tid] = a3;
    }
    group_barrier(8, 128);   // full-grid barrier (counter slot 8)

    // ---------------- Load weights + init state ----------------
    for (int idx = tid; idx < 512 * NC; idx += NTHR) {
        int kk = idx >> 5, jj = idx & 31;
        W1s[idx] = wec3ca1[kk * 512 + j0 + jj];
        W2s[idx] = wca1ec5[kk * 512 + j0 + jj];
    }
    for (int idx = tid; idx < 1024; idx += NTHR) wact_s[idx] = wca1act[idx];
    if (tid < 32) bias_s[tid] = ca1bias[j0 + tid];
    if (tid < 2)  actb_s[tid] = actbias[tid];
    for (int u = tid; u < RPG * 128; u += NTHR) {   // 16 rows x 128 float4
        int rr = u >> 7, kk = (u & 127) << 2;
        *(float4*)(x_s + rr * RPAD + kk) =
            *(const float4*)(ec3_last + (g * RPG + rr) * 512 + kk);
    }
    ec5s[tid] = ec5_last[b * 512 + col];
    __syncthreads();

    // ---------------- Main scan ----------------
    for (int t = 0; t < T; t++) {
        // Phase A: ca1 = clip(drive * (1 + sigmoid(ec3 @ W1)) - bias, 0, 1)
        float z   = gemm_zval(W1s, x_s, red);
        float drv = g_drive[t * 512 + col];
        float sg  = 1.f / (1.f + expf(-z));
        float ca1 = drv * (1.f + sg) - bias_s[j];
        ca1 = fminf(fmaxf(ca1, 0.f), 1.f);
        g_ex_ca1[b * 512 + col] = ca1;
        out[CA1HIS + (b * T + t) * 512 + col] = ca1;

        group_barrier(g, CPG);

        // gather full ca1 rows for this group (L1-bypass: other CTAs wrote it)
        for (int u = tid; u < RPG * 128; u += NTHR) {
            int rr = u >> 7, kk = (u & 127) << 2;
            *(float4*)(c_s + rr * RPAD + kk) =
                __ldcg((const float4*)(g_ex_ca1 + (g * RPG + rr) * 512 + kk));
        }
        __syncthreads();

        // act = ca1 @ wca1act + actbias  (column-CTA 0 of each group)
        if (ci == 0) {
            const int warp = tid >> 5, lane = tid & 31;
            float a0 = 0.f, a1 = 0.f;
            for (int k = lane; k < 512; k += 32) {
                float cv = c_s[warp * RPAD + k];
                a0 = fmaf(cv, wact_s[2 * k],     a0);
                a1 = fmaf(cv, wact_s[2 * k + 1], a1);
            }
#pragma unroll
            for (int o = 16; o; o >>= 1) {
                a0 += __shfl_down_sync(0xffffffffu, a0, o);
                a1 += __shfl_down_sync(0xffffffffu, a1, o);
            }
            if (lane == 0) {
                int bb = g * RPG + warp;
                out[ACT_OFF + (bb * T + t) * 2 + 0] = a0 + actb_s[0];
                out[ACT_OFF + (bb * T + t) * 2 + 1] = a1 + actb_s[1];
            }
        }

        // Phase B: ec5/ec3 update
        float z2 = gemm_zval(W2s, c_s, red);
        float e5 = ec5s[tid] + z2;                       // 10*TS == 1.0
        e5 = 0.69f + 0.3f / (1.f + expf(-4.f * (e5 - 0.3f)));
        float xo  = x_s[r * RPAD + col];
        float xin = ec3input[(b * T + t) * 512 + col];
        float e3  = e5 * xo + 0.6f * (1.f - xo) * xin;

        size_t mi = (size_t)(b * T + t) * 512 + col;
        bool msk;
        if (mmode == 0)      msk = nm_u8[mi] != 0;
        else if (mmode == 1) msk = nm_i32[mi] != 0;
        else                 msk = nm_f32[mi] != 0.0f;
        if (msk) e3 = 0.5f * e3 + 0.3f;

        ec5s[tid] = e5;
        g_ex_ec3[b * 512 + col] = e3;
        out[EC3HIS + (b * T + t) * 512 + col] = e3;
        out[EC5HIS + (b * T + t) * 512 + col] = e5;

        group_barrier(g, CPG);

        // gather full new ec3 rows (L1-bypass)
        for (int u = tid; u < RPG * 128; u += NTHR) {
            int rr = u >> 7, kk = (u & 127) << 2;
            *(float4*)(x_s + rr * RPAD + kk) =
                __ldcg((const float4*)(g_ex_ec3 + (g * RPG + rr) * 512 + kk));
        }
        __syncthreads();
    }

    // ---------------- Finals ----------------
    out[EC3F + b * 512 + col] = x_s[r * RPAD + col];
    out[EC5F + b * 512 + col] = ec5s[tid];
    out[CA1F + b * 512 + col] = __ldcg(g_ex_ca1 + b * 512 + col);
}

extern "C" void kernel_launch(void* const* d_in, const int* in_sizes, int n_in,
                              void* d_out, int out_size) {
    (void)in_sizes; (void)n_in; (void)out_size;

    // detect noise_mask encoding (uint8 / int32 / float32)
    init_flags_kernel<<<1, 1>>>();
    // scan first 4M words = 16MB; in-bounds for the smallest (uint8: 32MB) case
    detect_mask_kernel<<<256, 256>>>((const unsigned*)d_in[10], 4194304);

    cudaFuncSetAttribute(rnn_kernel, cudaFuncAttributeMaxDynamicSharedMemorySize,
                         SMEM_BYTES);
    rnn_kernel<<<NGRP * CPG, NTHR, SMEM_BYTES>>>(
        (const float*)d_in[0],      // ec3input
        (const float*)d_in[1],      // ec3_last
        (const float*)d_in[2],      // ec5_last
        (const float*)d_in[3],      // ca1_last (unused)
        (const float*)d_in[4],      // ca1bias
        (const float*)d_in[5],      // wca3ca1
        (const float*)d_in[6],      // wec3ca1
        (const float*)d_in[7],      // wca1ec5
        (const float*)d_in[8],      // wca1act
        (const float*)d_in[9],      // actbias
        d_in[10],                   // noise_mask (encoding auto-detected)
        (const int*)d_in[11],       // ca3order
        (float*)d_out);
}

// round 5
// speedup vs baseline: 1.0390x; 1.0390x over previous
#include <cuda_runtime.h>
#include <cstdint>

#define BS   128
#define T    512
#define E    512
#define NGRP 8          // batch groups
#define RPG  16         // batch rows per group
#define CPG  16         // CTAs per group (column split)
#define NC   32         // output cols per CTA
#define RPAD 516        // padded row stride (floats) for state tiles in smem
#define NTHR 512

// output layout offsets (float elements)
#define ACT_OFF  0
#define EC3HIS   131072
#define EC5HIS   33685504
#define CA1HIS   67239936
#define EC3F     100794368
#define EC5F     100859904
#define CA1F     100925440

// device scratch (allocation-free rule: static __device__ arrays)
__device__ float    g_drive[T * E];      // ca3drive[t][j]
__device__ float    g_ex_ca1[BS * E];    // per-step ca1 exchange
__device__ float    g_ex_ec3[BS * E];    // per-step ec3 exchange
__device__ unsigned g_bar_cnt[16];
__device__ unsigned g_bar_gen[16];
__device__ int      g_scan[128];         // per-CTA mask-encoding scan bits

// smem layout (floats)
#define SM_W1    0
#define SM_W2    (512 * NC)                  // 16384
#define SM_X     (2 * 512 * NC)              // 32768
#define SM_C     (SM_X + RPG * RPAD)         // 41024
#define SM_RED   (SM_C + RPG * RPAD)         // 49280
#define SM_WACT  (SM_RED + 2048)             // 51328
#define SM_BIAS  (SM_WACT + 1024)            // 52352
#define SM_ACTB  (SM_BIAS + 32)              // 52384
#define SM_FLOATS (SM_ACTB + 4)              // 52388
#define SMEM_BYTES (SM_FLOATS * 4)           // 209552 B

// packed fp32x2 helpers (sm_103a FFMA2 path)
__device__ __forceinline__ unsigned long long pack2(float x) {
    unsigned long long r;
    asm("mov.b64 %0, {%1, %1};" : "=l"(r) : "f"(x));
    return r;
}
__device__ __forceinline__ void fma2(unsigned long long& d,
                                     unsigned long long a, unsigned long long b) {
    asm("fma.rn.f32x2 %0, %1, %2, %0;" : "+l"(d) : "l"(a), "l"(b));
}

// sense-reversal barrier over n CTAs sharing counter idx
__device__ __forceinline__ void group_barrier(int idx, unsigned n) {
    __syncthreads();
    if (threadIdx.x == 0) {
        __threadfence();
        volatile unsigned* vgen = g_bar_gen;
        unsigned gen0 = vgen[idx];
        unsigned a = atomicAdd(&g_bar_cnt[idx], 1u);
        if (a == n - 1u) {
            g_bar_cnt[idx] = 0u;
            __threadfence();
            vgen[idx] = gen0 + 1u;
        } else {
            while (vgen[idx] == gen0) { }
        }
        __threadfence();
    }
    __syncthreads();
}

// z[16][32] = xs(16 x 512, RPAD stride) @ Ws(512 x 32), packed f32x2 math.
// 16 warps: warp = q + 4*p, q = row-quad, p = k-partition (128 k each).
// lane: rq = lane>>3 (row in quad), cg = lane&7 (4-col group).
// Returns z for output element (r = tid>>5, j = tid&31).
__device__ __forceinline__ float gemm_zval(const float* __restrict__ Ws,
                                           const float* __restrict__ xs,
                                           float* __restrict__ red) {
    const int tid  = threadIdx.x;
    const int warp = tid >> 5, lane = tid & 31;
    const int q  = warp & 3,  p  = warp >> 2;
    const int rq = lane >> 3, cg = lane & 7;
    const int r  = (q << 2) + rq;

    const float* xrow = xs + r * RPAD + (p << 7);
    // w block: row k occupies NC=32 floats = 8 ulonglong2; this lane reads 16B pair at cg*4
    const ulonglong2* wb = (const ulonglong2*)(Ws + (p << 7) * NC + (cg << 2));

    unsigned long long a0 = 0ull, a1 = 0ull;   // cols cg*4+{0,1} and {2,3}
#pragma unroll 8
    for (int k = 0; k < 128; k += 4) {
        float4 xv = *(const float4*)(xrow + k);
        unsigned long long x0 = pack2(xv.x), x1 = pack2(xv.y);
        unsigned long long x2 = pack2(xv.z), x3 = pack2(xv.w);
        ulonglong2 w0 = wb[(k + 0) * 8];
        ulonglong2 w1 = wb[(k + 1) * 8];
        ulonglong2 w2 = wb[(k + 2) * 8];
        ulonglong2 w3 = wb[(k + 3) * 8];
        fma2(a0, x0, w0.x); fma2(a1, x0, w0.y);
        fma2(a0, x1, w1.x); fma2(a1, x1, w1.y);
        fma2(a0, x2, w2.x); fma2(a1, x2, w2.y);
        fma2(a0, x3, w3.x); fma2(a1, x3, w3.y);
    }
    ulonglong2 accv; accv.x = a0; accv.y = a1;
    *(ulonglong2*)(red + (p * 16 + r) * NC + (cg << 2)) = accv;
    __syncthreads();
    const int rr = tid >> 5, jj = tid & 31;
    return red[rr * NC + jj] + red[512 + rr * NC + jj] +
           red[1024 + rr * NC + jj] + red[1536 + rr * NC + jj];
}

__global__ void __launch_bounds__(NTHR, 1)
rnn_kernel(const float* __restrict__ ec3input,
           const float* __restrict__ ec3_last,
           const float* __restrict__ ec5_last,
           const float* __restrict__ ca1_last,   // unused by reference
           const float* __restrict__ ca1bias,
           const float* __restrict__ wca3ca1,
           const float* __restrict__ wec3ca1,
           const float* __restrict__ wca1ec5,
           const float* __restrict__ wca1act,
           const float* __restrict__ actbias,
           const void* __restrict__ noise_mask,
           const int* __restrict__ ca3order,
           float* __restrict__ out) {
    extern __shared__ float smem[];
    float* W1s    = smem + SM_W1;
    float* W2s    = smem + SM_W2;
    float* x_s    = smem + SM_X;
    float* c_s    = smem + SM_C;
    float* red    = smem + SM_RED;
    float* wact_s = smem + SM_WACT;
    float* bias_s = smem + SM_BIAS;
    float* actb_s = smem + SM_ACTB;
    __shared__ int s_mmode;

    const int tid = threadIdx.x;
    const int bx  = blockIdx.x;
    const int g   = bx >> 4;     // batch group
    const int ci  = bx & 15;     // column CTA within group
    const int j0  = ci * NC;
    const int r   = tid >> 5;    // local row 0..15
    const int j   = tid & 31;    // local col 0..31
    const int b   = g * RPG + r; // global batch row
    const int col = j0 + j;      // global hidden col

    // ---------------- Phase 0a: mask-dtype scan ----------------
    // Scan 4M 32-bit words total (in-bounds for all encodings: uint8 buffer
    // is 32MB). Classify: any word outside {0,1,1.0f} => uint8 packing;
    // only {0,1} => int32; only {0,1.0f} => float32.
    if (tid == 0) g_scan[bx] = 0;
    __syncthreads();
    {
        const uint4* mw = (const uint4*)noise_mask;
        int bits = 0;
#pragma unroll
        for (int u = 0; u < 16; u++) {
            uint4 w = __ldcg(&mw[(size_t)bx * 8192 + (size_t)u * 512 + tid]);
            unsigned ws[4] = {w.x, w.y, w.z, w.w};
#pragma unroll
            for (int e = 0; e < 4; e++) {
                unsigned v = ws[e];
                if (v) {
                    if (v == 1u)               bits |= 2;
                    else if (v == 0x3F800000u) bits |= 4;
                    else                       bits |= 1;
                }
            }
        }
        if (bits) atomicOr(&g_scan[bx], bits);
    }

    // ---------------- Phase 0b: ca3drive precompute ----------------
    // CTA bx computes drive rows t = 4*bx .. 4*bx+3 (all 512 cols).
    {
        float* ca3v = x_s;  // reuse 4*512 floats of x_s region
        const float stepv = 614.4f / 511.0f;
        const int   ordc  = ca3order[tid];
        const float cen   = -51.2f + stepv * (float)ordc;
#pragma unroll
        for (int i = 0; i < 4; i++) {
            float d = cen - (float)(4 * bx + i);
            ca3v[i * 512 + tid] = expf(-d * d * 0.02f);
        }
        __syncthreads();
        float a0 = 0.f, a1 = 0.f, a2 = 0.f, a3 = 0.f;
#pragma unroll 4
        for (int c = 0; c < 512; c++) {
            float wv = wca3ca1[c * 512 + tid];
            a0 = fmaf(ca3v[c],        wv, a0);
            a1 = fmaf(ca3v[512 + c],  wv, a1);
            a2 = fmaf(ca3v[1024 + c], wv, a2);
            a3 = fmaf(ca3v[1536 + c], wv, a3);
        }
        g_drive[(4 * bx + 0) * 512 + tid] = a0;
        g_drive[(4 * bx + 1) * 512 + tid] = a1;
        g_drive[(4 * bx + 2) * 512 + tid] = a2;
        g_drive[(4 * bx + 3) * 512 + tid] = a3;
    }
    group_barrier(8, 128);   // full-grid barrier (counter slot 8)

    // reduce mask-encoding decision
    if (tid == 0) {
        int bits = 0;
        for (int i = 0; i < 128; i++) bits |= __ldcg(&g_scan[i]);
        s_mmode = (bits & 1) ? 0 : ((bits & 4) ? 2 : ((bits & 2) ? 1 : 0));
    }
    __syncthreads();
    const int mmode = s_mmode;   // 0 = uint8, 1 = int32, 2 = float32
    const uint8_t* nm_u8  = (const uint8_t*)noise_mask;
    const int*     nm_i32 = (const int*)noise_mask;
    const float*   nm_f32 = (const float*)noise_mask;

    // ---------------- Load weights + init state ----------------
    for (int idx = tid; idx < 512 * NC; idx += NTHR) {
        int kk = idx >> 5, jj = idx & 31;
        W1s[idx] = wec3ca1[kk * 512 + j0 + jj];
        W2s[idx] = wca1ec5[kk * 512 + j0 + jj];
    }
    for (int idx = tid; idx < 1024; idx += NTHR) wact_s[idx] = wca1act[idx];
    if (tid < 32) bias_s[tid] = ca1bias[j0 + tid];
    if (tid < 2)  actb_s[tid] = actbias[tid];
    for (int u = tid; u < RPG * 128; u += NTHR) {   // 16 rows x 128 float4
        int rr = u >> 7, kk = (u & 127) << 2;
        *(float4*)(x_s + rr * RPAD + kk) =
            *(const float4*)(ec3_last + (g * RPG + rr) * 512 + kk);
    }
    float ec5v = ec5_last[b * 512 + col];   // register-resident state
    float ec3v = ec3_last[b * 512 + col];
    __syncthreads();

    // ---------------- Main scan ----------------
    for (int t = 0; t < T; t++) {
        // Prefetch this step's global inputs; consumed ~2-5k cycles later,
        // hiding DRAM/L2 latency under the GEMMs.
        const size_t si = (size_t)(b * T + t) * 512 + col;
        float drv = __ldcg(&g_drive[t * 512 + col]);
        float xin = ec3input[si];
        bool  msk = (mmode == 0) ? (nm_u8[si] != 0)
                  : (mmode == 1) ? (nm_i32[si] != 0)
                                 : (nm_f32[si] != 0.0f);

        // Phase A: ca1 = clip(drive * (1 + sigmoid(ec3 @ W1)) - bias, 0, 1)
        float z   = gemm_zval(W1s, x_s, red);
        float sg  = 1.f / (1.f + expf(-z));
        float ca1 = drv * (1.f + sg) - bias_s[j];
        ca1 = fminf(fmaxf(ca1, 0.f), 1.f);
        g_ex_ca1[b * 512 + col] = ca1;
        out[CA1HIS + si] = ca1;

        group_barrier(g, CPG);

        // gather full ca1 rows for this group (L1-bypass: other CTAs wrote it)
        for (int u = tid; u < RPG * 128; u += NTHR) {
            int rr = u >> 7, kk = (u & 127) << 2;
            *(float4*)(c_s + rr * RPAD + kk) =
                __ldcg((const float4*)(g_ex_ca1 + (g * RPG + rr) * 512 + kk));
        }
        __syncthreads();

        // act = ca1 @ wca1act + actbias  (column-CTA 0 of each group)
        if (ci == 0) {
            const int warp = tid >> 5, lane = tid & 31;
            float a0 = 0.f, a1 = 0.f;
            for (int k = lane; k < 512; k += 32) {
                float cv = c_s[warp * RPAD + k];
                a0 = fmaf(cv, wact_s[2 * k],     a0);
                a1 = fmaf(cv, wact_s[2 * k + 1], a1);
            }
#pragma unroll
            for (int o = 16; o; o >>= 1) {
                a0 += __shfl_down_sync(0xffffffffu, a0, o);
                a1 += __shfl_down_sync(0xffffffffu, a1, o);
            }
            if (lane == 0) {
                int bb = g * RPG + warp;
                out[ACT_OFF + (bb * T + t) * 2 + 0] = a0 + actb_s[0];
                out[ACT_OFF + (bb * T + t) * 2 + 1] = a1 + actb_s[1];
            }
        }

        // Phase B: ec5/ec3 update
        float z2 = gemm_zval(W2s, c_s, red);
        float e5 = ec5v + z2;                            // 10*TS == 1.0
        e5 = 0.69f + 0.3f / (1.f + expf(-4.f * (e5 - 0.3f)));
        float e3 = e5 * ec3v + 0.6f * (1.f - ec3v) * xin;
        if (msk) e3 = 0.5f * e3 + 0.3f;
        ec5v = e5;
        ec3v = e3;
        g_ex_ec3[b * 512 + col] = e3;
        out[EC3HIS + si] = e3;
        out[EC5HIS + si] = e5;

        group_barrier(g, CPG);

        // gather full new ec3 rows (L1-bypass)
        for (int u = tid; u < RPG * 128; u += NTHR) {
            int rr = u >> 7, kk = (u & 127) << 2;
            *(float4*)(x_s + rr * RPAD + kk) =
                __ldcg((const float4*)(g_ex_ec3 + (g * RPG + rr) * 512 + kk));
        }
        __syncthreads();
    }

    // ---------------- Finals ----------------
    out[EC3F + b * 512 + col] = ec3v;
    out[EC5F + b * 512 + col] = ec5v;
    out[CA1F + b * 512 + col] = __ldcg(g_ex_ca1 + b * 512 + col);
}

extern "C" void kernel_launch(void* const* d_in, const int* in_sizes, int n_in,
                              void* d_out, int out_size) {
    (void)in_sizes; (void)n_in; (void)out_size;
    cudaFuncSetAttribute(rnn_kernel, cudaFuncAttributeMaxDynamicSharedMemorySize,
                         SMEM_BYTES);
    rnn_kernel<<<NGRP * CPG, NTHR, SMEM_BYTES>>>(
        (const float*)d_in[0],      // ec3input
        (const float*)d_in[1],      // ec3_last
        (const float*)d_in[2],      // ec5_last
        (const float*)d_in[3],      // ca1_last (unused)
        (const float*)d_in[4],      // ca1bias
        (const float*)d_in[5],      // wca3ca1
        (const float*)d_in[6],      // wec3ca1
        (const float*)d_in[7],      // wca1ec5
        (const float*)d_in[8],      // wca1act
        (const float*)d_in[9],      // actbias
        d_in[10],                   // noise_mask (encoding auto-detected)
        (const int*)d_in[11],       // ca3order
        (float*)d_out);
}

// round 6
// speedup vs baseline: 1.5325x; 1.4749x over previous
#include <cuda_runtime.h>
#include <cstdint>

#define BS   128
#define T    512
#define E    512
#define NGRP 8          // batch groups
#define RPG  16         // batch rows per group
#define CPG  16         // CTAs per group (column split)
#define NC   32         // output cols per CTA
#define RPAD 516        // padded row stride (floats); 4*RPAD%32==16 banks -> conflict-free x loads
#define NTHR 512

// output layout offsets (float elements)
#define ACT_OFF  0
#define EC3HIS   131072
#define EC5HIS   33685504
#define CA1HIS   67239936
#define EC3F     100794368
#define EC5F     100859904
#define CA1F     100925440

// device scratch (allocation-free rule: static __device__ arrays)
__device__ float    g_drive[T * E];      // ca3drive[t][j]
__device__ float    g_ex_ca1[BS * E];    // per-step ca1 exchange
__device__ float    g_ex_ec3[BS * E];    // per-step ec3 exchange
__device__ unsigned g_bar_cnt[16];
__device__ unsigned g_bar_gen[16];
__device__ int      g_scan[128];         // per-CTA mask-encoding scan bits

// smem layout (floats)
#define SM_W1    0
#define SM_W2    (512 * NC)                  // 16384
#define SM_X     (2 * 512 * NC)              // 32768
#define SM_C     (SM_X + RPG * RPAD)         // 41024
#define SM_RED   (SM_C + RPG * RPAD)         // 49280  (4096 floats = 8 tiles)
#define SM_WACT  (SM_RED + 4096)             // 53376
#define SM_BIAS  (SM_WACT + 1024)            // 54400
#define SM_ACTB  (SM_BIAS + 32)              // 54432
#define SM_FLOATS (SM_ACTB + 4)              // 54436
#define SMEM_BYTES (SM_FLOATS * 4)           // 217744 B

// packed fp32x2 helpers (sm_103a FFMA2 path)
__device__ __forceinline__ unsigned long long pack2(float x) {
    unsigned long long r;
    asm("mov.b64 %0, {%1, %1};" : "=l"(r) : "f"(x));
    return r;
}
__device__ __forceinline__ void fma2(unsigned long long& d,
                                     unsigned long long a, unsigned long long b) {
    asm("fma.rn.f32x2 %0, %1, %2, %0;" : "+l"(d) : "l"(a), "l"(b));
}

// sense-reversal barrier over n CTAs sharing counter idx
__device__ __forceinline__ void group_barrier(int idx, unsigned n) {
    __syncthreads();
    if (threadIdx.x == 0) {
        __threadfence();
        volatile unsigned* vgen = g_bar_gen;
        unsigned gen0 = vgen[idx];
        unsigned a = atomicAdd(&g_bar_cnt[idx], 1u);
        if (a == n - 1u) {
            g_bar_cnt[idx] = 0u;
            __threadfence();
            vgen[idx] = gen0 + 1u;
        } else {
            while (vgen[idx] == gen0) { }
        }
        __threadfence();
    }
    __syncthreads();
}

// z[16][32] = xs(16 x 512, RPAD stride) @ Ws(512 x 32).
// Register outer-product tiling: warp w owns k-slice [32w, 32w+32) of the FULL
// 16x32 output tile. Lane (rg = lane>>3, cg = lane&7) accumulates a 4x4 tile:
// rows rg+4i (i=0..3), cols 4cg..4cg+3 (as two f32x2 pairs per row).
// Partials reduced through smem in two 8-warp batches.
// Returns z for output element (r = tid>>5, j = tid&31), i.e. red[tid].
__device__ __forceinline__ float gemm_zval(const float* __restrict__ Ws,
                                           const float* __restrict__ xs,
                                           float* __restrict__ red) {
    const int tid  = threadIdx.x;
    const int warp = tid >> 5, lane = tid & 31;
    const int rg = lane >> 3, cg = lane & 7;

    const float* xb = xs + rg * RPAD + (warp << 5);              // row rg, +4*RPAD per i
    const ulonglong2* wb = (const ulonglong2*)(Ws + (warp << 5) * NC + (cg << 2));

    unsigned long long a00=0ull,a01=0ull,a10=0ull,a11=0ull,
                       a20=0ull,a21=0ull,a30=0ull,a31=0ull;
#pragma unroll
    for (int kb = 0; kb < 32; kb += 4) {
        float4 x0 = *(const float4*)(xb + 0 * 4 * RPAD + kb);
        float4 x1 = *(const float4*)(xb + 1 * 4 * RPAD + kb);
        float4 x2 = *(const float4*)(xb + 2 * 4 * RPAD + kb);
        float4 x3 = *(const float4*)(xb + 3 * 4 * RPAD + kb);
        ulonglong2 w0 = wb[(kb + 0) * 8];
        ulonglong2 w1 = wb[(kb + 1) * 8];
        ulonglong2 w2 = wb[(kb + 2) * 8];
        ulonglong2 w3 = wb[(kb + 3) * 8];
        unsigned long long p;
        p = pack2(x0.x); fma2(a00, p, w0.x); fma2(a01, p, w0.y);
        p = pack2(x0.y); fma2(a00, p, w1.x); fma2(a01, p, w1.y);
        p = pack2(x0.z); fma2(a00, p, w2.x); fma2(a01, p, w2.y);
        p = pack2(x0.w); fma2(a00, p, w3.x); fma2(a01, p, w3.y);
        p = pack2(x1.x); fma2(a10, p, w0.x); fma2(a11, p, w0.y);
        p = pack2(x1.y); fma2(a10, p, w1.x); fma2(a11, p, w1.y);
        p = pack2(x1.z); fma2(a10, p, w2.x); fma2(a11, p, w2.y);
        p = pack2(x1.w); fma2(a10, p, w3.x); fma2(a11, p, w3.y);
        p = pack2(x2.x); fma2(a20, p, w0.x); fma2(a21, p, w0.y);
        p = pack2(x2.y); fma2(a20, p, w1.x); fma2(a21, p, w1.y);
        p = pack2(x2.z); fma2(a20, p, w2.x); fma2(a21, p, w2.y);
        p = pack2(x2.w); fma2(a20, p, w3.x); fma2(a21, p, w3.y);
        p = pack2(x3.x); fma2(a30, p, w0.x); fma2(a31, p, w0.y);
        p = pack2(x3.y); fma2(a30, p, w1.x); fma2(a31, p, w1.y);
        p = pack2(x3.z); fma2(a30, p, w2.x); fma2(a31, p, w2.y);
        p = pack2(x3.w); fma2(a30, p, w3.x); fma2(a31, p, w3.y);
    }

    // ----- reduce 16 warp-partials via smem, two 8-warp batches -----
    unsigned long long* buf64 = (unsigned long long*)red;
    // lane's tile row i lives at float offset (rg+4i)*32 + cg*4 within a tile
    const int toff = rg * 16 + cg * 2;   // u64 offset; +64 per i (4 rows * 16)
    float zsum;

    __syncthreads();                     // guard buf reuse
    if (warp < 8) {
        unsigned long long* d = buf64 + (warp << 8) + toff;
        ulonglong2 v;
        v.x = a00; v.y = a01; *(ulonglong2*)(d)       = v;
        v.x = a10; v.y = a11; *(ulonglong2*)(d + 64)  = v;
        v.x = a20; v.y = a21; *(ulonglong2*)(d + 128) = v;
        v.x = a30; v.y = a31; *(ulonglong2*)(d + 192) = v;
    }
    __syncthreads();
    {
        float s0 = red[tid]        + red[512  + tid];
        float s1 = red[1024 + tid] + red[1536 + tid];
        float s2 = red[2048 + tid] + red[2560 + tid];
        float s3 = red[3072 + tid] + red[3584 + tid];
        zsum = (s0 + s1) + (s2 + s3);
    }
    __syncthreads();
    if (warp >= 8) {
        unsigned long long* d = buf64 + ((warp - 8) << 8) + toff;
        ulonglong2 v;
        v.x = a00; v.y = a01; *(ulonglong2*)(d)       = v;
        v.x = a10; v.y = a11; *(ulonglong2*)(d + 64)  = v;
        v.x = a20; v.y = a21; *(ulonglong2*)(d + 128) = v;
        v.x = a30; v.y = a31; *(ulonglong2*)(d + 192) = v;
    }
    __syncthreads();
    {
        float s0 = red[tid]        + red[512  + tid];
        float s1 = red[1024 + tid] + red[1536 + tid];
        float s2 = red[2048 + tid] + red[2560 + tid];
        float s3 = red[3072 + tid] + red[3584 + tid];
        zsum += (s0 + s1) + (s2 + s3);
    }
    return zsum;
}

__global__ void __launch_bounds__(NTHR, 1)
rnn_kernel(const float* __restrict__ ec3input,
           const float* __restrict__ ec3_last,
           const float* __restrict__ ec5_last,
           const float* __restrict__ ca1_last,   // unused by reference
           const float* __restrict__ ca1bias,
           const float* __restrict__ wca3ca1,
           const float* __restrict__ wec3ca1,
           const float* __restrict__ wca1ec5,
           const float* __restrict__ wca1act,
           const float* __restrict__ actbias,
           const void* __restrict__ noise_mask,
           const int* __restrict__ ca3order,
           float* __restrict__ out) {
    extern __shared__ float smem[];
    float* W1s    = smem + SM_W1;
    float* W2s    = smem + SM_W2;
    float* x_s    = smem + SM_X;
    float* c_s    = smem + SM_C;
    float* red    = smem + SM_RED;
    float* wact_s = smem + SM_WACT;
    float* bias_s = smem + SM_BIAS;
    float* actb_s = smem + SM_ACTB;
    __shared__ int s_mmode;

    const int tid = threadIdx.x;
    const int bx  = blockIdx.x;
    const int g   = bx >> 4;     // batch group
    const int ci  = bx & 15;     // column CTA within group
    const int j0  = ci * NC;
    const int r   = tid >> 5;    // local row 0..15
    const int j   = tid & 31;    // local col 0..31
    const int b   = g * RPG + r; // global batch row
    const int col = j0 + j;      // global hidden col

    // ---------------- Phase 0a: mask-dtype scan ----------------
    if (tid == 0) g_scan[bx] = 0;
    __syncthreads();
    {
        const uint4* mw = (const uint4*)noise_mask;
        int bits = 0;
#pragma unroll
        for (int u = 0; u < 16; u++) {
            uint4 w = __ldcg(&mw[(size_t)bx * 8192 + (size_t)u * 512 + tid]);
            unsigned ws[4] = {w.x, w.y, w.z, w.w};
#pragma unroll
            for (int e = 0; e < 4; e++) {
                unsigned v = ws[e];
                if (v) {
                    if (v == 1u)               bits |= 2;
                    else if (v == 0x3F800000u) bits |= 4;
                    else                       bits |= 1;
                }
            }
        }
        if (bits) atomicOr(&g_scan[bx], bits);
    }

    // ---------------- Phase 0b: ca3drive precompute ----------------
    {
        float* ca3v = x_s;  // reuse 4*512 floats of x_s region
        const float stepv = 614.4f / 511.0f;
        const int   ordc  = ca3order[tid];
        const float cen   = -51.2f + stepv * (float)ordc;
#pragma unroll
        for (int i = 0; i < 4; i++) {
            float d = cen - (float)(4 * bx + i);
            ca3v[i * 512 + tid] = expf(-d * d * 0.02f);
        }
        __syncthreads();
        float a0 = 0.f, a1 = 0.f, a2 = 0.f, a3 = 0.f;
#pragma unroll 4
        for (int c = 0; c < 512; c++) {
            float wv = wca3ca1[c * 512 + tid];
            a0 = fmaf(ca3v[c],        wv, a0);
            a1 = fmaf(ca3v[512 + c],  wv, a1);
            a2 = fmaf(ca3v[1024 + c], wv, a2);
            a3 = fmaf(ca3v[1536 + c], wv, a3);
        }
        g_drive[(4 * bx + 0) * 512 + tid] = a0;
        g_drive[(4 * bx + 1) * 512 + tid] = a1;
        g_drive[(4 * bx + 2) * 512 + tid] = a2;
        g_drive[(4 * bx + 3) * 512 + tid] = a3;
    }
    group_barrier(8, 128);   // full-grid barrier (counter slot 8)

    // reduce mask-encoding decision
    if (tid == 0) {
        int bits = 0;
        for (int i = 0; i < 128; i++) bits |= __ldcg(&g_scan[i]);
        s_mmode = (bits & 1) ? 0 : ((bits & 4) ? 2 : ((bits & 2) ? 1 : 0));
    }
    __syncthreads();
    const int mmode = s_mmode;   // 0 = uint8, 1 = int32, 2 = float32
    const uint8_t* nm_u8  = (const uint8_t*)noise_mask;
    const int*     nm_i32 = (const int*)noise_mask;
    const float*   nm_f32 = (const float*)noise_mask;

    // ---------------- Load weights + init state ----------------
    for (int idx = tid; idx < 512 * NC; idx += NTHR) {
        int kk = idx >> 5, jj = idx & 31;
        W1s[idx] = wec3ca1[kk * 512 + j0 + jj];
        W2s[idx] = wca1ec5[kk * 512 + j0 + jj];
    }
    for (int idx = tid; idx < 1024; idx += NTHR) wact_s[idx] = wca1act[idx];
    if (tid < 32) bias_s[tid] = ca1bias[j0 + tid];
    if (tid < 2)  actb_s[tid] = actbias[tid];
    for (int u = tid; u < RPG * 128; u += NTHR) {   // 16 rows x 128 float4
        int rr = u >> 7, kk = (u & 127) << 2;
        *(float4*)(x_s + rr * RPAD + kk) =
            *(const float4*)(ec3_last + (g * RPG + rr) * 512 + kk);
    }
    float ec5v = ec5_last[b * 512 + col];   // register-resident state
    float ec3v = ec3_last[b * 512 + col];
    __syncthreads();

    // ---------------- Main scan ----------------
    for (int t = 0; t < T; t++) {
        // Prefetch this step's global inputs (hidden under phase-A GEMM)
        const size_t si = (size_t)(b * T + t) * 512 + col;
        float drv = __ldcg(&g_drive[t * 512 + col]);
        float xin = ec3input[si];
        bool  msk = (mmode == 0) ? (nm_u8[si] != 0)
                  : (mmode == 1) ? (nm_i32[si] != 0)
                                 : (nm_f32[si] != 0.0f);

        // Phase A: ca1 = clip(drive * (1 + sigmoid(ec3 @ W1)) - bias, 0, 1)
        float z   = gemm_zval(W1s, x_s, red);
        float sg  = 1.f / (1.f + expf(-z));
        float ca1 = drv * (1.f + sg) - bias_s[j];
        ca1 = fminf(fmaxf(ca1, 0.f), 1.f);
        g_ex_ca1[b * 512 + col] = ca1;
        out[CA1HIS + si] = ca1;

        group_barrier(g, CPG);

        // gather full ca1 rows for this group (L1-bypass: other CTAs wrote it)
        for (int u = tid; u < RPG * 128; u += NTHR) {
            int rr = u >> 7, kk = (u & 127) << 2;
            *(float4*)(c_s + rr * RPAD + kk) =
                __ldcg((const float4*)(g_ex_ca1 + (g * RPG + rr) * 512 + kk));
        }
        __syncthreads();

        // act = ca1 @ wca1act + actbias  (column-CTA 0 of each group)
        if (ci == 0) {
            const int warp = tid >> 5, lane = tid & 31;
            float a0 = 0.f, a1 = 0.f;
            for (int k = lane; k < 512; k += 32) {
                float cv = c_s[warp * RPAD + k];
                a0 = fmaf(cv, wact_s[2 * k],     a0);
                a1 = fmaf(cv, wact_s[2 * k + 1], a1);
            }
#pragma unroll
            for (int o = 16; o; o >>= 1) {
                a0 += __shfl_down_sync(0xffffffffu, a0, o);
                a1 += __shfl_down_sync(0xffffffffu, a1, o);
            }
            if (lane == 0) {
                int bb = g * RPG + warp;
                out[ACT_OFF + (bb * T + t) * 2 + 0] = a0 + actb_s[0];
                out[ACT_OFF + (bb * T + t) * 2 + 1] = a1 + actb_s[1];
            }
        }

        // Phase B: ec5/ec3 update
        float z2 = gemm_zval(W2s, c_s, red);
        float e5 = ec5v + z2;                            // 10*TS == 1.0
        e5 = 0.69f + 0.3f / (1.f + expf(-4.f * (e5 - 0.3f)));
        float e3 = e5 * ec3v + 0.6f * (1.f - ec3v) * xin;
        if (msk) e3 = 0.5f * e3 + 0.3f;
        ec5v = e5;
        ec3v = e3;
        g_ex_ec3[b * 512 + col] = e3;
        out[EC3HIS + si] = e3;
        out[EC5HIS + si] = e5;

        group_barrier(g, CPG);

        // gather full new ec3 rows (L1-bypass)
        for (int u = tid; u < RPG * 128; u += NTHR) {
            int rr = u >> 7, kk = (u & 127) << 2;
            *(float4*)(x_s + rr * RPAD + kk) =
                __ldcg((const float4*)(g_ex_ec3 + (g * RPG + rr) * 512 + kk));
        }
        __syncthreads();
    }

    // ---------------- Finals ----------------
    out[EC3F + b * 512 + col] = ec3v;
    out[EC5F + b * 512 + col] = ec5v;
    out[CA1F + b * 512 + col] = __ldcg(g_ex_ca1 + b * 512 + col);
}

extern "C" void kernel_launch(void* const* d_in, const int* in_sizes, int n_in,
                              void* d_out, int out_size) {
    (void)in_sizes; (void)n_in; (void)out_size;
    cudaFuncSetAttribute(rnn_kernel, cudaFuncAttributeMaxDynamicSharedMemorySize,
                         SMEM_BYTES);
    rnn_kernel<<<NGRP * CPG, NTHR, SMEM_BYTES>>>(
        (const float*)d_in[0],      // ec3input
        (const float*)d_in[1],      // ec3_last
        (const float*)d_in[2],      // ec5_last
        (const float*)d_in[3],      // ca1_last (unused)
        (const float*)d_in[4],      // ca1bias
        (const float*)d_in[5],      // wca3ca1
        (const float*)d_in[6],      // wec3ca1
        (const float*)d_in[7],      // wca1ec5
        (const float*)d_in[8],      // wca1act
        (const float*)d_in[9],      // actbias
        d_in[10],                   // noise_mask (encoding auto-detected)
        (const int*)d_in[11],       // ca3order
        (float*)d_out);
}